// round 13
// baseline (speedup 1.0000x reference)
#include <cuda_runtime.h>
#include <cuda_fp16.h>
#include <cstdint>

#define D 128
#define MAX_N 50176
#define MAX_E 810000
#define ROWP (D + 8)           // padded half-row: 136 halves = 272B

__device__ __half g_hs[(size_t)MAX_N * D];     // half(h * outdeg^-0.5)
__device__ __half g_agg[(size_t)MAX_N * D];    // f16 atomic accumulator
__device__ __half g_wh[D * D];                 // half(W)
__device__ int    g_deg[2 * MAX_N];            // [0,MAX_N): outdeg  [MAX_N,..): indeg

// ---------------------------------------------------------------------------
// 1: degree counts — int4 loads, 4 edges per thread
// ---------------------------------------------------------------------------
__global__ void degree_kernel(const int* __restrict__ src,
                              const int* __restrict__ dst, int E) {
    int i = blockIdx.x * blockDim.x + threadIdx.x;
    int e = i * 4;
    if (e + 3 < E) {
        int4 s4 = *reinterpret_cast<const int4*>(src + e);
        int4 d4 = *reinterpret_cast<const int4*>(dst + e);
        atomicAdd(&g_deg[s4.x], 1);
        atomicAdd(&g_deg[s4.y], 1);
        atomicAdd(&g_deg[s4.z], 1);
        atomicAdd(&g_deg[s4.w], 1);
        atomicAdd(&g_deg[MAX_N + d4.x], 1);
        atomicAdd(&g_deg[MAX_N + d4.y], 1);
        atomicAdd(&g_deg[MAX_N + d4.z], 1);
        atomicAdd(&g_deg[MAX_N + d4.w], 1);
    } else {
        for (int j = 0; j < 4; j++) {
            int ee = e + j;
            if (ee < E) {
                atomicAdd(&g_deg[src[ee]], 1);
                atomicAdd(&g_deg[MAX_N + dst[ee]], 1);
            }
        }
    }
}

// ---------------------------------------------------------------------------
// 2: fused prep: blocks [0, nh) scale h -> f16;  blocks [nh, nh+8) convert W
// ---------------------------------------------------------------------------
__global__ void prep_kernel(const float* __restrict__ h,
                            const float* __restrict__ W, int N, int nh) {
    if ((int)blockIdx.x >= nh) {
        int idx = (blockIdx.x - nh) * blockDim.x + threadIdx.x;
        if (idx >= D * D / 8) return;
        const float4* wp = reinterpret_cast<const float4*>(W) + (size_t)idx * 2;
        float4 a = wp[0];
        float4 b = wp[1];
        __half2 packs[4];
        packs[0] = __floats2half2_rn(a.x, a.y);
        packs[1] = __floats2half2_rn(a.z, a.w);
        packs[2] = __floats2half2_rn(b.x, b.y);
        packs[3] = __floats2half2_rn(b.z, b.w);
        reinterpret_cast<uint4*>(g_wh)[idx] = *reinterpret_cast<uint4*>(packs);
        return;
    }
    int idx = blockIdx.x * blockDim.x + threadIdx.x;   // over N*16 groups of 8
    if (idx >= N * (D / 8)) return;
    int row = idx >> 4;
    float s = rsqrtf((float)g_deg[row]);
    const float4* hp = reinterpret_cast<const float4*>(h) + (size_t)idx * 2;
    float4 a = hp[0];
    float4 b = hp[1];
    __half2 packs[4];
    packs[0] = __floats2half2_rn(a.x * s, a.y * s);
    packs[1] = __floats2half2_rn(a.z * s, a.w * s);
    packs[2] = __floats2half2_rn(b.x * s, b.y * s);
    packs[3] = __floats2half2_rn(b.z * s, b.w * s);
    reinterpret_cast<uint4*>(g_hs)[idx] = *reinterpret_cast<uint4*>(packs);
}

// ---------------------------------------------------------------------------
// 3: edge scatter, 16 lanes/edge, 4 edges per thread (software-pipelined),
//    f16x2 vector reduction
// ---------------------------------------------------------------------------
__global__ void scatter_kernel(const int* __restrict__ src,
                               const int* __restrict__ dst,
                               const int* __restrict__ dist, int E, int Eq) {
    int gid  = blockIdx.x * blockDim.x + threadIdx.x;
    int e0   = gid >> 4;
    int lane = gid & 15;
    if (e0 >= Eq) return;

    int ei[4];
    bool has[4];
    #pragma unroll
    for (int j = 0; j < 4; j++) {
        ei[j]  = e0 + j * Eq;
        has[j] = (ei[j] < E);
    }

    // phase 1: edge descriptors
    int s[4], d[4], di[4];
    #pragma unroll
    for (int j = 0; j < 4; j++) {
        s[j] = di[j] = 0; d[j] = 0;
        if (has[j]) {
            s[j]  = __ldg(src + ei[j]);
            d[j]  = __ldg(dst + ei[j]);
            di[j] = __ldg(dist + ei[j]);
        }
    }

    // phase 2: gathers (4 independent loads in flight)
    uint4 v[4];
    #pragma unroll
    for (int j = 0; j < 4; j++) {
        v[j] = make_uint4(0, 0, 0, 0);
        if (has[j])
            v[j] = reinterpret_cast<const uint4*>(g_hs + (size_t)s[j] * D)[lane];
    }

    // phase 3: scale + reduce
    #pragma unroll
    for (int j = 0; j < 4; j++) {
        if (!has[j]) continue;
        __half2 w2 = __float2half2_rn(__int_as_float((127 - di[j]) << 23));
        __half2* hv = reinterpret_cast<__half2*>(&v[j]);
        hv[0] = __hmul2(hv[0], w2);
        hv[1] = __hmul2(hv[1], w2);
        hv[2] = __hmul2(hv[2], w2);
        hv[3] = __hmul2(hv[3], w2);
        __half* p = g_agg + (size_t)d[j] * D + lane * 8;
        asm volatile("red.global.add.noftz.v4.f16x2 [%0], {%1,%2,%3,%4};"
                     :: "l"(p), "r"(v[j].x), "r"(v[j].y), "r"(v[j].z), "r"(v[j].w)
                     : "memory");
    }
}

// ---------------------------------------------------------------------------
// 4: tensor-core GEMM: out = (f16(g_agg) @ g_wh) * indeg^-1.5 + bias
// ---------------------------------------------------------------------------
__device__ __forceinline__ uint32_t smem_u32(const void* p) {
    return (uint32_t)__cvta_generic_to_shared(p);
}

__global__ __launch_bounds__(256)
void gemm_kernel(const float* __restrict__ bias, float* __restrict__ out, int N) {
    extern __shared__ __half sm[];
    __half* As = sm;                 // [128][ROWP]
    __half* Ws = sm + 128 * ROWP;    // [k][n] padded
    int tid  = threadIdx.x;
    int row0 = blockIdx.x * 128;

    // Issue the A-tile gmem loads FIRST (long latency), then fill Ws while
    // they are in flight.
    uint4 areg[8];
    int   am[8], ac[8];
    #pragma unroll
    for (int jj = 0; jj < 8; jj++) {
        int i  = tid + jj * 256;
        int m  = i >> 4;
        int c8 = (i & 15) * 8;
        am[jj] = m; ac[jj] = c8;
        int grow = row0 + m;
        areg[jj] = make_uint4(0, 0, 0, 0);
        if (grow < N)
            areg[jj] = *reinterpret_cast<const uint4*>(g_agg + (size_t)grow * D + c8);
    }
    for (int i = tid; i < D * D / 8; i += 256) {
        int k  = i >> 4;
        int c8 = (i & 15) * 8;
        *reinterpret_cast<uint4*>(Ws + k * ROWP + c8) =
            reinterpret_cast<const uint4*>(g_wh)[i];
    }
    #pragma unroll
    for (int jj = 0; jj < 8; jj++)
        *reinterpret_cast<uint4*>(As + am[jj] * ROWP + ac[jj]) = areg[jj];
    __syncthreads();

    int wid  = tid >> 5;
    int lane = tid & 31;
    int mrow = wid * 16;

    float acc[16][4];
    #pragma unroll
    for (int nb = 0; nb < 16; nb++)
        #pragma unroll
        for (int j = 0; j < 4; j++) acc[nb][j] = 0.f;

    uint32_t As_u = smem_u32(As);
    uint32_t Ws_u = smem_u32(Ws);
    int lr = lane & 15;
    int lc = (lane >> 4) << 3;
    int bg = lane >> 3;
    int br = lane & 7;

    #pragma unroll
    for (int kk = 0; kk < 8; kk++) {
        uint32_t a_addr = As_u + (uint32_t)(((mrow + lr) * ROWP) + kk * 16 + lc) * 2;
        uint32_t a0, a1, a2, a3;
        asm volatile("ldmatrix.sync.aligned.m8n8.x4.shared.b16 {%0,%1,%2,%3}, [%4];"
                     : "=r"(a0), "=r"(a1), "=r"(a2), "=r"(a3) : "r"(a_addr));
        #pragma unroll
        for (int nb2 = 0; nb2 < 8; nb2++) {
            int brow = kk * 16 + (bg & 1) * 8 + br;
            int bcol = nb2 * 16 + (bg >> 1) * 8;
            uint32_t b_addr = Ws_u + (uint32_t)(brow * ROWP + bcol) * 2;
            uint32_t b0, b1, b2, b3;
            asm volatile("ldmatrix.sync.aligned.m8n8.x4.trans.shared.b16 {%0,%1,%2,%3}, [%4];"
                         : "=r"(b0), "=r"(b1), "=r"(b2), "=r"(b3) : "r"(b_addr));
            asm volatile("mma.sync.aligned.m16n8k16.row.col.f32.f16.f16.f32 "
                         "{%0,%1,%2,%3},{%4,%5,%6,%7},{%8,%9},{%0,%1,%2,%3};"
                         : "+f"(acc[nb2 * 2][0]), "+f"(acc[nb2 * 2][1]),
                           "+f"(acc[nb2 * 2][2]), "+f"(acc[nb2 * 2][3])
                         : "r"(a0), "r"(a1), "r"(a2), "r"(a3), "r"(b0), "r"(b1));
            asm volatile("mma.sync.aligned.m16n8k16.row.col.f32.f16.f16.f32 "
                         "{%0,%1,%2,%3},{%4,%5,%6,%7},{%8,%9},{%0,%1,%2,%3};"
                         : "+f"(acc[nb2 * 2 + 1][0]), "+f"(acc[nb2 * 2 + 1][1]),
                           "+f"(acc[nb2 * 2 + 1][2]), "+f"(acc[nb2 * 2 + 1][3])
                         : "r"(a0), "r"(a1), "r"(a2), "r"(a3), "r"(b2), "r"(b3));
        }
    }

    int r0 = row0 + mrow + (lane >> 2);
    int r1 = r0 + 8;
    float s0 = 0.f, s1 = 0.f;
    if (r0 < N) { float id = (float)g_deg[MAX_N + r0]; s0 = rsqrtf(id) / id; }
    if (r1 < N) { float id = (float)g_deg[MAX_N + r1]; s1 = rsqrtf(id) / id; }

    #pragma unroll
    for (int nb = 0; nb < 16; nb++) {
        int col = nb * 8 + (lane & 3) * 2;
        float b0 = __ldg(bias + col);
        float b1 = __ldg(bias + col + 1);
        if (r0 < N) {
            float2 o = make_float2(acc[nb][0] * s0 + b0, acc[nb][1] * s0 + b1);
            *reinterpret_cast<float2*>(out + (size_t)r0 * D + col) = o;
        }
        if (r1 < N) {
            float2 o = make_float2(acc[nb][2] * s1 + b0, acc[nb][3] * s1 + b1);
            *reinterpret_cast<float2*>(out + (size_t)r1 * D + col) = o;
        }
    }
}

// ---------------------------------------------------------------------------
extern "C" void kernel_launch(void* const* d_in, const int* in_sizes, int n_in,
                              void* d_out, int out_size) {
    const float* h    = (const float*)d_in[0];
    const int*   src  = (const int*)  d_in[1];
    const int*   dst  = (const int*)  d_in[2];
    const int*   dist = (const int*)  d_in[3];
    const float* W    = (const float*)d_in[4];
    const float* bias = (const float*)d_in[5];
    float*       out  = (float*)d_out;

    int N = in_sizes[0] / D;
    int E = in_sizes[1];

    void *agg_p, *deg_p;
    cudaGetSymbolAddress(&agg_p, g_agg);
    cudaGetSymbolAddress(&deg_p, g_deg);
    cudaMemsetAsync(deg_p, 0, 2 * MAX_N * sizeof(int));
    cudaMemsetAsync(agg_p, 0, (size_t)N * D * sizeof(__half));

    int dthreads = (E + 3) / 4;
    degree_kernel<<<(dthreads + 255) / 256, 256>>>(src, dst, E);

    int nh = (N * (D / 8) + 255) / 256;
    prep_kernel<<<nh + 8, 256>>>(h, W, N, nh);

    int Eq = (E + 3) / 4;
    long long sthreads = (long long)Eq * 16;
    scatter_kernel<<<(unsigned)((sthreads + 255) / 256), 256>>>(src, dst, dist, E, Eq);

    int smem_bytes = 2 * 128 * ROWP * sizeof(__half);  // ~68 KB
    cudaFuncSetAttribute(gemm_kernel,
                         cudaFuncAttributeMaxDynamicSharedMemorySize, smem_bytes);
    gemm_kernel<<<(N + 127) / 128, 256, smem_bytes>>>(bias, out, N);
}

// round 14
// speedup vs baseline: 1.1266x; 1.1266x over previous
#include <cuda_runtime.h>
#include <cuda_fp16.h>
#include <cstdint>

#define D 128
#define MAX_N 50176
#define MAX_E 810000
#define ROWP (D + 8)           // padded half-row: 136 halves = 272B

__device__ __half g_hs[(size_t)MAX_N * D];     // half(h * outdeg^-0.5)
__device__ __half g_agg[(size_t)MAX_N * D];    // f16 atomic accumulator
__device__ __half g_wh[D * D];                 // half(W)
__device__ int    g_deg[2 * MAX_N];            // [0,MAX_N): outdeg  [MAX_N,..): indeg

// ---------------------------------------------------------------------------
// 1: degree counts (int2-vectorized, 2 edges per thread)  [R12 form]
// ---------------------------------------------------------------------------
__global__ void degree_kernel(const int* __restrict__ src,
                              const int* __restrict__ dst, int E) {
    int i = blockIdx.x * blockDim.x + threadIdx.x;
    int e = i * 2;
    if (e + 1 < E) {
        int2 s2 = *reinterpret_cast<const int2*>(src + e);
        int2 d2 = *reinterpret_cast<const int2*>(dst + e);
        atomicAdd(&g_deg[s2.x], 1);
        atomicAdd(&g_deg[s2.y], 1);
        atomicAdd(&g_deg[MAX_N + d2.x], 1);
        atomicAdd(&g_deg[MAX_N + d2.y], 1);
    } else if (e < E) {
        atomicAdd(&g_deg[src[e]], 1);
        atomicAdd(&g_deg[MAX_N + dst[e]], 1);
    }
}

// ---------------------------------------------------------------------------
// 2: fused prep: blocks [0, nh) scale h -> f16;  blocks [nh, nh+8) convert W
// ---------------------------------------------------------------------------
__global__ void prep_kernel(const float* __restrict__ h,
                            const float* __restrict__ W, int N, int nh) {
    if ((int)blockIdx.x >= nh) {
        int idx = (blockIdx.x - nh) * blockDim.x + threadIdx.x;
        if (idx >= D * D / 8) return;
        const float4* wp = reinterpret_cast<const float4*>(W) + (size_t)idx * 2;
        float4 a = wp[0];
        float4 b = wp[1];
        __half2 packs[4];
        packs[0] = __floats2half2_rn(a.x, a.y);
        packs[1] = __floats2half2_rn(a.z, a.w);
        packs[2] = __floats2half2_rn(b.x, b.y);
        packs[3] = __floats2half2_rn(b.z, b.w);
        reinterpret_cast<uint4*>(g_wh)[idx] = *reinterpret_cast<uint4*>(packs);
        return;
    }
    int idx = blockIdx.x * blockDim.x + threadIdx.x;   // over N*16 groups of 8
    if (idx >= N * (D / 8)) return;
    int row = idx >> 4;
    float s = rsqrtf((float)g_deg[row]);
    const float4* hp = reinterpret_cast<const float4*>(h) + (size_t)idx * 2;
    float4 a = hp[0];
    float4 b = hp[1];
    __half2 packs[4];
    packs[0] = __floats2half2_rn(a.x * s, a.y * s);
    packs[1] = __floats2half2_rn(a.z * s, a.w * s);
    packs[2] = __floats2half2_rn(b.x * s, b.y * s);
    packs[3] = __floats2half2_rn(b.z * s, b.w * s);
    reinterpret_cast<uint4*>(g_hs)[idx] = *reinterpret_cast<uint4*>(packs);
}

// ---------------------------------------------------------------------------
// 3: edge scatter, 16 lanes/edge, 2 edges per thread (software-pipelined)
//    [R12 form — proven optimum]
// ---------------------------------------------------------------------------
__global__ void scatter_kernel(const int* __restrict__ src,
                               const int* __restrict__ dst,
                               const int* __restrict__ dist, int E, int Ehalf) {
    int gid  = blockIdx.x * blockDim.x + threadIdx.x;
    int e1   = gid >> 4;
    int lane = gid & 15;
    if (e1 >= Ehalf) return;
    int e2 = e1 + Ehalf;
    bool has2 = (e2 < E);

    int s1  = __ldg(src + e1);
    int d1  = __ldg(dst + e1);
    int di1 = __ldg(dist + e1);
    int s2 = 0, d2 = 0, di2 = 0;
    if (has2) {
        s2  = __ldg(src + e2);
        d2  = __ldg(dst + e2);
        di2 = __ldg(dist + e2);
    }

    uint4 v1 = reinterpret_cast<const uint4*>(g_hs + (size_t)s1 * D)[lane];
    uint4 v2 = make_uint4(0, 0, 0, 0);
    if (has2)
        v2 = reinterpret_cast<const uint4*>(g_hs + (size_t)s2 * D)[lane];

    __half2 w1 = __float2half2_rn(__int_as_float((127 - di1) << 23));
    __half2* hv1 = reinterpret_cast<__half2*>(&v1);
    hv1[0] = __hmul2(hv1[0], w1);
    hv1[1] = __hmul2(hv1[1], w1);
    hv1[2] = __hmul2(hv1[2], w1);
    hv1[3] = __hmul2(hv1[3], w1);
    __half* p1 = g_agg + (size_t)d1 * D + lane * 8;
    asm volatile("red.global.add.noftz.v4.f16x2 [%0], {%1,%2,%3,%4};"
                 :: "l"(p1), "r"(v1.x), "r"(v1.y), "r"(v1.z), "r"(v1.w)
                 : "memory");

    if (has2) {
        __half2 w2 = __float2half2_rn(__int_as_float((127 - di2) << 23));
        __half2* hv2 = reinterpret_cast<__half2*>(&v2);
        hv2[0] = __hmul2(hv2[0], w2);
        hv2[1] = __hmul2(hv2[1], w2);
        hv2[2] = __hmul2(hv2[2], w2);
        hv2[3] = __hmul2(hv2[3], w2);
        __half* p2 = g_agg + (size_t)d2 * D + lane * 8;
        asm volatile("red.global.add.noftz.v4.f16x2 [%0], {%1,%2,%3,%4};"
                     :: "l"(p2), "r"(v2.x), "r"(v2.y), "r"(v2.z), "r"(v2.w)
                     : "memory");
    }
}

// ---------------------------------------------------------------------------
// 4: tensor-core GEMM, 2 row-tiles per block (Ws fill amortized, better waves)
// ---------------------------------------------------------------------------
__device__ __forceinline__ uint32_t smem_u32(const void* p) {
    return (uint32_t)__cvta_generic_to_shared(p);
}

__global__ __launch_bounds__(256)
void gemm_kernel(const float* __restrict__ bias, float* __restrict__ out,
                 int N, int ntiles, int tstride) {
    extern __shared__ __half sm[];
    __half* As = sm;                 // [128][ROWP]
    __half* Ws = sm + 128 * ROWP;    // [k][n] padded
    int tid  = threadIdx.x;

    // Ws <- g_wh once per block
    for (int i = tid; i < D * D / 8; i += 256) {
        int k  = i >> 4;
        int c8 = (i & 15) * 8;
        *reinterpret_cast<uint4*>(Ws + k * ROWP + c8) =
            reinterpret_cast<const uint4*>(g_wh)[i];
    }

    int wid  = tid >> 5;
    int lane = tid & 31;
    int mrow = wid * 16;

    uint32_t As_u = smem_u32(As);
    uint32_t Ws_u = smem_u32(Ws);
    int lr = lane & 15;
    int lc = (lane >> 4) << 3;
    int bg = lane >> 3;
    int br = lane & 7;

    for (int t = blockIdx.x; t < ntiles; t += tstride) {
        int row0 = t * 128;

        // A tile fill (tile>first: wait until previous iteration's reads done)
        if (t != (int)blockIdx.x) __syncthreads();
        for (int i = tid; i < 128 * (D / 8); i += 256) {
            int m  = i >> 4;
            int c8 = (i & 15) * 8;
            int grow = row0 + m;
            uint4 v = make_uint4(0, 0, 0, 0);
            if (grow < N)
                v = *reinterpret_cast<const uint4*>(g_agg + (size_t)grow * D + c8);
            *reinterpret_cast<uint4*>(As + m * ROWP + c8) = v;
        }
        __syncthreads();

        float acc[16][4];
        #pragma unroll
        for (int nb = 0; nb < 16; nb++)
            #pragma unroll
            for (int j = 0; j < 4; j++) acc[nb][j] = 0.f;

        #pragma unroll
        for (int kk = 0; kk < 8; kk++) {
            uint32_t a_addr = As_u + (uint32_t)(((mrow + lr) * ROWP) + kk * 16 + lc) * 2;
            uint32_t a0, a1, a2, a3;
            asm volatile("ldmatrix.sync.aligned.m8n8.x4.shared.b16 {%0,%1,%2,%3}, [%4];"
                         : "=r"(a0), "=r"(a1), "=r"(a2), "=r"(a3) : "r"(a_addr));
            #pragma unroll
            for (int nb2 = 0; nb2 < 8; nb2++) {
                int brow = kk * 16 + (bg & 1) * 8 + br;
                int bcol = nb2 * 16 + (bg >> 1) * 8;
                uint32_t b_addr = Ws_u + (uint32_t)(brow * ROWP + bcol) * 2;
                uint32_t b0, b1, b2, b3;
                asm volatile("ldmatrix.sync.aligned.m8n8.x4.trans.shared.b16 {%0,%1,%2,%3}, [%4];"
                             : "=r"(b0), "=r"(b1), "=r"(b2), "=r"(b3) : "r"(b_addr));
                asm volatile("mma.sync.aligned.m16n8k16.row.col.f32.f16.f16.f32 "
                             "{%0,%1,%2,%3},{%4,%5,%6,%7},{%8,%9},{%0,%1,%2,%3};"
                             : "+f"(acc[nb2 * 2][0]), "+f"(acc[nb2 * 2][1]),
                               "+f"(acc[nb2 * 2][2]), "+f"(acc[nb2 * 2][3])
                             : "r"(a0), "r"(a1), "r"(a2), "r"(a3), "r"(b0), "r"(b1));
                asm volatile("mma.sync.aligned.m16n8k16.row.col.f32.f16.f16.f32 "
                             "{%0,%1,%2,%3},{%4,%5,%6,%7},{%8,%9},{%0,%1,%2,%3};"
                             : "+f"(acc[nb2 * 2 + 1][0]), "+f"(acc[nb2 * 2 + 1][1]),
                               "+f"(acc[nb2 * 2 + 1][2]), "+f"(acc[nb2 * 2 + 1][3])
                             : "r"(a0), "r"(a1), "r"(a2), "r"(a3), "r"(b2), "r"(b3));
            }
        }

        int r0 = row0 + mrow + (lane >> 2);
        int r1 = r0 + 8;
        float s0 = 0.f, s1 = 0.f;
        if (r0 < N) { float id = (float)g_deg[MAX_N + r0]; s0 = rsqrtf(id) / id; }
        if (r1 < N) { float id = (float)g_deg[MAX_N + r1]; s1 = rsqrtf(id) / id; }

        #pragma unroll
        for (int nb = 0; nb < 16; nb++) {
            int col = nb * 8 + (lane & 3) * 2;
            float b0 = __ldg(bias + col);
            float b1 = __ldg(bias + col + 1);
            if (r0 < N) {
                float2 o = make_float2(acc[nb][0] * s0 + b0, acc[nb][1] * s0 + b1);
                *reinterpret_cast<float2*>(out + (size_t)r0 * D + col) = o;
            }
            if (r1 < N) {
                float2 o = make_float2(acc[nb][2] * s1 + b0, acc[nb][3] * s1 + b1);
                *reinterpret_cast<float2*>(out + (size_t)r1 * D + col) = o;
            }
        }
    }
}

// ---------------------------------------------------------------------------
extern "C" void kernel_launch(void* const* d_in, const int* in_sizes, int n_in,
                              void* d_out, int out_size) {
    const float* h    = (const float*)d_in[0];
    const int*   src  = (const int*)  d_in[1];
    const int*   dst  = (const int*)  d_in[2];
    const int*   dist = (const int*)  d_in[3];
    const float* W    = (const float*)d_in[4];
    const float* bias = (const float*)d_in[5];
    float*       out  = (float*)d_out;

    int N = in_sizes[0] / D;
    int E = in_sizes[1];

    void *agg_p, *deg_p;
    cudaGetSymbolAddress(&agg_p, g_agg);
    cudaGetSymbolAddress(&deg_p, g_deg);
    cudaMemsetAsync(deg_p, 0, 2 * MAX_N * sizeof(int));
    cudaMemsetAsync(agg_p, 0, (size_t)N * D * sizeof(__half));

    int dthreads = (E + 1) / 2;
    degree_kernel<<<(dthreads + 255) / 256, 256>>>(src, dst, E);

    int nh = (N * (D / 8) + 255) / 256;
    prep_kernel<<<nh + 8, 256>>>(h, W, N, nh);

    int Ehalf = (E + 1) / 2;
    long long sthreads = (long long)Ehalf * 16;
    scatter_kernel<<<(unsigned)((sthreads + 255) / 256), 256>>>(src, dst, dist, E, Ehalf);

    int ntiles  = (N + 127) / 128;           // 391
    int tstride = (ntiles + 1) / 2;          // 196: each block does <=2 tiles
    int smem_bytes = 2 * 128 * ROWP * sizeof(__half);  // ~68 KB
    cudaFuncSetAttribute(gemm_kernel,
                         cudaFuncAttributeMaxDynamicSharedMemorySize, smem_bytes);
    gemm_kernel<<<tstride, 256, smem_bytes>>>(bias, out, N, ntiles, tstride);
}

// round 15
// speedup vs baseline: 1.1276x; 1.0008x over previous
#include <cuda_runtime.h>
#include <cuda_fp16.h>
#include <cstdint>

#define D 128
#define MAX_N 50176
#define MAX_E 810000
#define ROWP (D + 8)           // padded half-row: 136 halves = 272B

__device__ __half g_hs[(size_t)MAX_N * D];     // half(h * outdeg^-0.5)
__device__ __half g_agg[(size_t)MAX_N * D];    // f16 atomic accumulator
__device__ __half g_wh[D * D];                 // half(W)
__device__ int    g_deg[2 * MAX_N];            // [0,MAX_N): outdeg  [MAX_N,..): indeg

// ---------------------------------------------------------------------------
// 1: degree counts (int2, 2 edges/thread) + fused g_agg zeroing
// ---------------------------------------------------------------------------
__global__ void degree_kernel(const int* __restrict__ src,
                              const int* __restrict__ dst, int E, int aggN4) {
    int i = blockIdx.x * blockDim.x + threadIdx.x;
    int total = gridDim.x * blockDim.x;

    // zero the f16 accumulator (grid-stride, uint4 stores)
    for (int j = i; j < aggN4; j += total)
        reinterpret_cast<uint4*>(g_agg)[j] = make_uint4(0, 0, 0, 0);

    int e = i * 2;
    if (e + 1 < E) {
        int2 s2 = *reinterpret_cast<const int2*>(src + e);
        int2 d2 = *reinterpret_cast<const int2*>(dst + e);
        atomicAdd(&g_deg[s2.x], 1);
        atomicAdd(&g_deg[s2.y], 1);
        atomicAdd(&g_deg[MAX_N + d2.x], 1);
        atomicAdd(&g_deg[MAX_N + d2.y], 1);
    } else if (e < E) {
        atomicAdd(&g_deg[src[e]], 1);
        atomicAdd(&g_deg[MAX_N + dst[e]], 1);
    }
}

// ---------------------------------------------------------------------------
// 2: fused prep: blocks [0, nh) scale h -> f16;  blocks [nh, nh+8) convert W
// ---------------------------------------------------------------------------
__global__ void prep_kernel(const float* __restrict__ h,
                            const float* __restrict__ W, int N, int nh) {
    if ((int)blockIdx.x >= nh) {
        int idx = (blockIdx.x - nh) * blockDim.x + threadIdx.x;
        if (idx >= D * D / 8) return;
        const float4* wp = reinterpret_cast<const float4*>(W) + (size_t)idx * 2;
        float4 a = wp[0];
        float4 b = wp[1];
        __half2 packs[4];
        packs[0] = __floats2half2_rn(a.x, a.y);
        packs[1] = __floats2half2_rn(a.z, a.w);
        packs[2] = __floats2half2_rn(b.x, b.y);
        packs[3] = __floats2half2_rn(b.z, b.w);
        reinterpret_cast<uint4*>(g_wh)[idx] = *reinterpret_cast<uint4*>(packs);
        return;
    }
    int idx = blockIdx.x * blockDim.x + threadIdx.x;   // over N*16 groups of 8
    if (idx >= N * (D / 8)) return;
    int row = idx >> 4;
    float s = rsqrtf((float)g_deg[row]);
    const float4* hp = reinterpret_cast<const float4*>(h) + (size_t)idx * 2;
    float4 a = hp[0];
    float4 b = hp[1];
    __half2 packs[4];
    packs[0] = __floats2half2_rn(a.x * s, a.y * s);
    packs[1] = __floats2half2_rn(a.z * s, a.w * s);
    packs[2] = __floats2half2_rn(b.x * s, b.y * s);
    packs[3] = __floats2half2_rn(b.z * s, b.w * s);
    reinterpret_cast<uint4*>(g_hs)[idx] = *reinterpret_cast<uint4*>(packs);
}

// ---------------------------------------------------------------------------
// 3: edge scatter, 16 lanes/edge, 2 edges per thread  [R12 proven form]
// ---------------------------------------------------------------------------
__global__ void scatter_kernel(const int* __restrict__ src,
                               const int* __restrict__ dst,
                               const int* __restrict__ dist, int E, int Ehalf) {
    int gid  = blockIdx.x * blockDim.x + threadIdx.x;
    int e1   = gid >> 4;
    int lane = gid & 15;
    if (e1 >= Ehalf) return;
    int e2 = e1 + Ehalf;
    bool has2 = (e2 < E);

    int s1  = __ldg(src + e1);
    int d1  = __ldg(dst + e1);
    int di1 = __ldg(dist + e1);
    int s2 = 0, d2 = 0, di2 = 0;
    if (has2) {
        s2  = __ldg(src + e2);
        d2  = __ldg(dst + e2);
        di2 = __ldg(dist + e2);
    }

    uint4 v1 = reinterpret_cast<const uint4*>(g_hs + (size_t)s1 * D)[lane];
    uint4 v2 = make_uint4(0, 0, 0, 0);
    if (has2)
        v2 = reinterpret_cast<const uint4*>(g_hs + (size_t)s2 * D)[lane];

    __half2 w1 = __float2half2_rn(__int_as_float((127 - di1) << 23));
    __half2* hv1 = reinterpret_cast<__half2*>(&v1);
    hv1[0] = __hmul2(hv1[0], w1);
    hv1[1] = __hmul2(hv1[1], w1);
    hv1[2] = __hmul2(hv1[2], w1);
    hv1[3] = __hmul2(hv1[3], w1);
    __half* p1 = g_agg + (size_t)d1 * D + lane * 8;
    asm volatile("red.global.add.noftz.v4.f16x2 [%0], {%1,%2,%3,%4};"
                 :: "l"(p1), "r"(v1.x), "r"(v1.y), "r"(v1.z), "r"(v1.w)
                 : "memory");

    if (has2) {
        __half2 w2 = __float2half2_rn(__int_as_float((127 - di2) << 23));
        __half2* hv2 = reinterpret_cast<__half2*>(&v2);
        hv2[0] = __hmul2(hv2[0], w2);
        hv2[1] = __hmul2(hv2[1], w2);
        hv2[2] = __hmul2(hv2[2], w2);
        hv2[3] = __hmul2(hv2[3], w2);
        __half* p2 = g_agg + (size_t)d2 * D + lane * 8;
        asm volatile("red.global.add.noftz.v4.f16x2 [%0], {%1,%2,%3,%4};"
                     :: "l"(p2), "r"(v2.x), "r"(v2.y), "r"(v2.z), "r"(v2.w)
                     : "memory");
    }
}

// ---------------------------------------------------------------------------
// 4: tensor-core GEMM.  M-tile 64, 8 warps = 4 M-subtiles x 2 N-halves.
// Each warp: 16 rows x 64 cols -> acc[8][4] (32 regs), 5 LDSM per k-chunk.
// ---------------------------------------------------------------------------
__device__ __forceinline__ uint32_t smem_u32(const void* p) {
    return (uint32_t)__cvta_generic_to_shared(p);
}

__global__ __launch_bounds__(256)
void gemm_kernel(const float* __restrict__ bias, float* __restrict__ out, int N) {
    extern __shared__ __half sm[];
    __half* As = sm;                 // [64][ROWP]
    __half* Ws = sm + 64 * ROWP;     // [128][ROWP]
    int tid  = threadIdx.x;
    int row0 = blockIdx.x * 64;

    // Ws <- g_wh : 2048 uint4
    for (int i = tid; i < D * D / 8; i += 256) {
        int k  = i >> 4;
        int c8 = (i & 15) * 8;
        *reinterpret_cast<uint4*>(Ws + k * ROWP + c8) =
            reinterpret_cast<const uint4*>(g_wh)[i];
    }
    // A tile : 64 rows x 16 uint4
    for (int i = tid; i < 64 * (D / 8); i += 256) {
        int m  = i >> 4;
        int c8 = (i & 15) * 8;
        int grow = row0 + m;
        uint4 v = make_uint4(0, 0, 0, 0);
        if (grow < N)
            v = *reinterpret_cast<const uint4*>(g_agg + (size_t)grow * D + c8);
        *reinterpret_cast<uint4*>(As + m * ROWP + c8) = v;
    }
    __syncthreads();

    int wid  = tid >> 5;
    int lane = tid & 31;
    int mrow = (wid & 3) * 16;       // M subtile within the 64-row tile
    int nc0  = (wid >> 2) * 64;      // N half

    float acc[8][4];
    #pragma unroll
    for (int nb = 0; nb < 8; nb++)
        #pragma unroll
        for (int j = 0; j < 4; j++) acc[nb][j] = 0.f;

    uint32_t As_u = smem_u32(As);
    uint32_t Ws_u = smem_u32(Ws);
    int lr = lane & 15;
    int lc = (lane >> 4) << 3;
    int bg = lane >> 3;
    int br = lane & 7;

    #pragma unroll
    for (int kk = 0; kk < 8; kk++) {
        uint32_t a_addr = As_u + (uint32_t)(((mrow + lr) * ROWP) + kk * 16 + lc) * 2;
        uint32_t a0, a1, a2, a3;
        asm volatile("ldmatrix.sync.aligned.m8n8.x4.shared.b16 {%0,%1,%2,%3}, [%4];"
                     : "=r"(a0), "=r"(a1), "=r"(a2), "=r"(a3) : "r"(a_addr));
        #pragma unroll
        for (int nb2 = 0; nb2 < 4; nb2++) {
            int brow = kk * 16 + (bg & 1) * 8 + br;
            int bcol = nc0 + nb2 * 16 + (bg >> 1) * 8;
            uint32_t b_addr = Ws_u + (uint32_t)(brow * ROWP + bcol) * 2;
            uint32_t b0, b1, b2, b3;
            asm volatile("ldmatrix.sync.aligned.m8n8.x4.trans.shared.b16 {%0,%1,%2,%3}, [%4];"
                         : "=r"(b0), "=r"(b1), "=r"(b2), "=r"(b3) : "r"(b_addr));
            asm volatile("mma.sync.aligned.m16n8k16.row.col.f32.f16.f16.f32 "
                         "{%0,%1,%2,%3},{%4,%5,%6,%7},{%8,%9},{%0,%1,%2,%3};"
                         : "+f"(acc[nb2 * 2][0]), "+f"(acc[nb2 * 2][1]),
                           "+f"(acc[nb2 * 2][2]), "+f"(acc[nb2 * 2][3])
                         : "r"(a0), "r"(a1), "r"(a2), "r"(a3), "r"(b0), "r"(b1));
            asm volatile("mma.sync.aligned.m16n8k16.row.col.f32.f16.f16.f32 "
                         "{%0,%1,%2,%3},{%4,%5,%6,%7},{%8,%9},{%0,%1,%2,%3};"
                         : "+f"(acc[nb2 * 2 + 1][0]), "+f"(acc[nb2 * 2 + 1][1]),
                           "+f"(acc[nb2 * 2 + 1][2]), "+f"(acc[nb2 * 2 + 1][3])
                         : "r"(a0), "r"(a1), "r"(a2), "r"(a3), "r"(b2), "r"(b3));
        }
    }

    int r0 = row0 + mrow + (lane >> 2);
    int r1 = r0 + 8;
    float s0 = 0.f, s1 = 0.f;
    if (r0 < N) { float id = (float)g_deg[MAX_N + r0]; s0 = rsqrtf(id) / id; }
    if (r1 < N) { float id = (float)g_deg[MAX_N + r1]; s1 = rsqrtf(id) / id; }

    #pragma unroll
    for (int nb = 0; nb < 8; nb++) {
        int col = nc0 + nb * 8 + (lane & 3) * 2;
        float b0 = __ldg(bias + col);
        float b1 = __ldg(bias + col + 1);
        if (r0 < N) {
            float2 o = make_float2(acc[nb][0] * s0 + b0, acc[nb][1] * s0 + b1);
            *reinterpret_cast<float2*>(out + (size_t)r0 * D + col) = o;
        }
        if (r1 < N) {
            float2 o = make_float2(acc[nb][2] * s1 + b0, acc[nb][3] * s1 + b1);
            *reinterpret_cast<float2*>(out + (size_t)r1 * D + col) = o;
        }
    }
}

// ---------------------------------------------------------------------------
extern "C" void kernel_launch(void* const* d_in, const int* in_sizes, int n_in,
                              void* d_out, int out_size) {
    const float* h    = (const float*)d_in[0];
    const int*   src  = (const int*)  d_in[1];
    const int*   dst  = (const int*)  d_in[2];
    const int*   dist = (const int*)  d_in[3];
    const float* W    = (const float*)d_in[4];
    const float* bias = (const float*)d_in[5];
    float*       out  = (float*)d_out;

    int N = in_sizes[0] / D;
    int E = in_sizes[1];

    void* deg_p;
    cudaGetSymbolAddress(&deg_p, g_deg);
    cudaMemsetAsync(deg_p, 0, 2 * MAX_N * sizeof(int));

    int dthreads = (E + 1) / 2;
    int aggN4 = N * (D / 8);     // uint4 count of g_agg
    degree_kernel<<<(dthreads + 255) / 256, 256>>>(src, dst, E, aggN4);

    int nh = (N * (D / 8) + 255) / 256;
    prep_kernel<<<nh + 8, 256>>>(h, W, N, nh);

    int Ehalf = (E + 1) / 2;
    long long sthreads = (long long)Ehalf * 16;
    scatter_kernel<<<(unsigned)((sthreads + 255) / 256), 256>>>(src, dst, dist, E, Ehalf);

    int smem_bytes = (64 + 128) * ROWP * sizeof(__half);  // ~52 KB
    cudaFuncSetAttribute(gemm_kernel,
                         cudaFuncAttributeMaxDynamicSharedMemorySize, smem_bytes);
    gemm_kernel<<<(N + 63) / 64, 256, smem_bytes>>>(bias, out, N);
}

// round 16
// speedup vs baseline: 1.1547x; 1.0241x over previous
#include <cuda_runtime.h>
#include <cuda_fp16.h>
#include <cstdint>

#define D 128
#define MAX_N 50176
#define MAX_E 810000
#define ROWP (D + 8)           // padded half-row: 136 halves = 272B

__device__ __half g_hs[(size_t)MAX_N * D];     // half(h * outdeg^-0.5)
__device__ __half g_agg[(size_t)MAX_N * D];    // f16 atomic accumulator
__device__ __half g_wh[D * D];                 // half(W)
__device__ int    g_deg[2 * MAX_N];            // [0,MAX_N): outdeg  [MAX_N,..): indeg

// ---------------------------------------------------------------------------
// 1: degree counts (int2, 2 edges/thread) + fused g_agg zeroing  [R12+R15]
// ---------------------------------------------------------------------------
__global__ void degree_kernel(const int* __restrict__ src,
                              const int* __restrict__ dst, int E, int aggN4) {
    int i = blockIdx.x * blockDim.x + threadIdx.x;
    int total = gridDim.x * blockDim.x;

    // zero the f16 accumulator (grid-stride, uint4 stores)
    for (int j = i; j < aggN4; j += total)
        reinterpret_cast<uint4*>(g_agg)[j] = make_uint4(0, 0, 0, 0);

    int e = i * 2;
    if (e + 1 < E) {
        int2 s2 = *reinterpret_cast<const int2*>(src + e);
        int2 d2 = *reinterpret_cast<const int2*>(dst + e);
        atomicAdd(&g_deg[s2.x], 1);
        atomicAdd(&g_deg[s2.y], 1);
        atomicAdd(&g_deg[MAX_N + d2.x], 1);
        atomicAdd(&g_deg[MAX_N + d2.y], 1);
    } else if (e < E) {
        atomicAdd(&g_deg[src[e]], 1);
        atomicAdd(&g_deg[MAX_N + dst[e]], 1);
    }
}

// ---------------------------------------------------------------------------
// 2: fused prep: blocks [0, nh) scale h -> f16;  blocks [nh, nh+8) convert W
// ---------------------------------------------------------------------------
__global__ void prep_kernel(const float* __restrict__ h,
                            const float* __restrict__ W, int N, int nh) {
    if ((int)blockIdx.x >= nh) {
        int idx = (blockIdx.x - nh) * blockDim.x + threadIdx.x;
        if (idx >= D * D / 8) return;
        const float4* wp = reinterpret_cast<const float4*>(W) + (size_t)idx * 2;
        float4 a = wp[0];
        float4 b = wp[1];
        __half2 packs[4];
        packs[0] = __floats2half2_rn(a.x, a.y);
        packs[1] = __floats2half2_rn(a.z, a.w);
        packs[2] = __floats2half2_rn(b.x, b.y);
        packs[3] = __floats2half2_rn(b.z, b.w);
        reinterpret_cast<uint4*>(g_wh)[idx] = *reinterpret_cast<uint4*>(packs);
        return;
    }
    int idx = blockIdx.x * blockDim.x + threadIdx.x;   // over N*16 groups of 8
    if (idx >= N * (D / 8)) return;
    int row = idx >> 4;
    float s = rsqrtf((float)g_deg[row]);
    const float4* hp = reinterpret_cast<const float4*>(h) + (size_t)idx * 2;
    float4 a = hp[0];
    float4 b = hp[1];
    __half2 packs[4];
    packs[0] = __floats2half2_rn(a.x * s, a.y * s);
    packs[1] = __floats2half2_rn(a.z * s, a.w * s);
    packs[2] = __floats2half2_rn(b.x * s, b.y * s);
    packs[3] = __floats2half2_rn(b.z * s, b.w * s);
    reinterpret_cast<uint4*>(g_hs)[idx] = *reinterpret_cast<uint4*>(packs);
}

// ---------------------------------------------------------------------------
// 3: edge scatter, 16 lanes/edge, 2 edges per thread  [R12 proven form]
// ---------------------------------------------------------------------------
__global__ void scatter_kernel(const int* __restrict__ src,
                               const int* __restrict__ dst,
                               const int* __restrict__ dist, int E, int Ehalf) {
    int gid  = blockIdx.x * blockDim.x + threadIdx.x;
    int e1   = gid >> 4;
    int lane = gid & 15;
    if (e1 >= Ehalf) return;
    int e2 = e1 + Ehalf;
    bool has2 = (e2 < E);

    int s1  = __ldg(src + e1);
    int d1  = __ldg(dst + e1);
    int di1 = __ldg(dist + e1);
    int s2 = 0, d2 = 0, di2 = 0;
    if (has2) {
        s2  = __ldg(src + e2);
        d2  = __ldg(dst + e2);
        di2 = __ldg(dist + e2);
    }

    uint4 v1 = reinterpret_cast<const uint4*>(g_hs + (size_t)s1 * D)[lane];
    uint4 v2 = make_uint4(0, 0, 0, 0);
    if (has2)
        v2 = reinterpret_cast<const uint4*>(g_hs + (size_t)s2 * D)[lane];

    __half2 w1 = __float2half2_rn(__int_as_float((127 - di1) << 23));
    __half2* hv1 = reinterpret_cast<__half2*>(&v1);
    hv1[0] = __hmul2(hv1[0], w1);
    hv1[1] = __hmul2(hv1[1], w1);
    hv1[2] = __hmul2(hv1[2], w1);
    hv1[3] = __hmul2(hv1[3], w1);
    __half* p1 = g_agg + (size_t)d1 * D + lane * 8;
    asm volatile("red.global.add.noftz.v4.f16x2 [%0], {%1,%2,%3,%4};"
                 :: "l"(p1), "r"(v1.x), "r"(v1.y), "r"(v1.z), "r"(v1.w)
                 : "memory");

    if (has2) {
        __half2 w2 = __float2half2_rn(__int_as_float((127 - di2) << 23));
        __half2* hv2 = reinterpret_cast<__half2*>(&v2);
        hv2[0] = __hmul2(hv2[0], w2);
        hv2[1] = __hmul2(hv2[1], w2);
        hv2[2] = __hmul2(hv2[2], w2);
        hv2[3] = __hmul2(hv2[3], w2);
        __half* p2 = g_agg + (size_t)d2 * D + lane * 8;
        asm volatile("red.global.add.noftz.v4.f16x2 [%0], {%1,%2,%3,%4};"
                     :: "l"(p2), "r"(v2.x), "r"(v2.y), "r"(v2.z), "r"(v2.w)
                     : "memory");
    }
}

// ---------------------------------------------------------------------------
// 4: tensor-core GEMM  [R12 exact form — best measured at 19.9us]
// ---------------------------------------------------------------------------
__device__ __forceinline__ uint32_t smem_u32(const void* p) {
    return (uint32_t)__cvta_generic_to_shared(p);
}

__global__ __launch_bounds__(256)
void gemm_kernel(const float* __restrict__ bias, float* __restrict__ out, int N) {
    extern __shared__ __half sm[];
    __half* As = sm;                 // [128][ROWP]
    __half* Ws = sm + 128 * ROWP;    // [k][n] padded
    int tid  = threadIdx.x;
    int row0 = blockIdx.x * 128;

    for (int i = tid; i < D * D / 8; i += 256) {
        int k  = i >> 4;
        int c8 = (i & 15) * 8;
        *reinterpret_cast<uint4*>(Ws + k * ROWP + c8) =
            reinterpret_cast<const uint4*>(g_wh)[i];
    }
    for (int i = tid; i < 128 * (D / 8); i += 256) {
        int m  = i >> 4;
        int c8 = (i & 15) * 8;
        int grow = row0 + m;
        uint4 v = make_uint4(0, 0, 0, 0);
        if (grow < N)
            v = *reinterpret_cast<const uint4*>(g_agg + (size_t)grow * D + c8);
        *reinterpret_cast<uint4*>(As + m * ROWP + c8) = v;
    }
    __syncthreads();

    int wid  = tid >> 5;
    int lane = tid & 31;
    int mrow = wid * 16;

    float acc[16][4];
    #pragma unroll
    for (int nb = 0; nb < 16; nb++)
        #pragma unroll
        for (int j = 0; j < 4; j++) acc[nb][j] = 0.f;

    uint32_t As_u = smem_u32(As);
    uint32_t Ws_u = smem_u32(Ws);
    int lr = lane & 15;
    int lc = (lane >> 4) << 3;
    int bg = lane >> 3;
    int br = lane & 7;

    #pragma unroll
    for (int kk = 0; kk < 8; kk++) {
        uint32_t a_addr = As_u + (uint32_t)(((mrow + lr) * ROWP) + kk * 16 + lc) * 2;
        uint32_t a0, a1, a2, a3;
        asm volatile("ldmatrix.sync.aligned.m8n8.x4.shared.b16 {%0,%1,%2,%3}, [%4];"
                     : "=r"(a0), "=r"(a1), "=r"(a2), "=r"(a3) : "r"(a_addr));
        #pragma unroll
        for (int nb2 = 0; nb2 < 8; nb2++) {
            int brow = kk * 16 + (bg & 1) * 8 + br;
            int bcol = nb2 * 16 + (bg >> 1) * 8;
            uint32_t b_addr = Ws_u + (uint32_t)(brow * ROWP + bcol) * 2;
            uint32_t b0, b1, b2, b3;
            asm volatile("ldmatrix.sync.aligned.m8n8.x4.trans.shared.b16 {%0,%1,%2,%3}, [%4];"
                         : "=r"(b0), "=r"(b1), "=r"(b2), "=r"(b3) : "r"(b_addr));
            asm volatile("mma.sync.aligned.m16n8k16.row.col.f32.f16.f16.f32 "
                         "{%0,%1,%2,%3},{%4,%5,%6,%7},{%8,%9},{%0,%1,%2,%3};"
                         : "+f"(acc[nb2 * 2][0]), "+f"(acc[nb2 * 2][1]),
                           "+f"(acc[nb2 * 2][2]), "+f"(acc[nb2 * 2][3])
                         : "r"(a0), "r"(a1), "r"(a2), "r"(a3), "r"(b0), "r"(b1));
            asm volatile("mma.sync.aligned.m16n8k16.row.col.f32.f16.f16.f32 "
                         "{%0,%1,%2,%3},{%4,%5,%6,%7},{%8,%9},{%0,%1,%2,%3};"
                         : "+f"(acc[nb2 * 2 + 1][0]), "+f"(acc[nb2 * 2 + 1][1]),
                           "+f"(acc[nb2 * 2 + 1][2]), "+f"(acc[nb2 * 2 + 1][3])
                         : "r"(a0), "r"(a1), "r"(a2), "r"(a3), "r"(b2), "r"(b3));
        }
    }

    int r0 = row0 + mrow + (lane >> 2);
    int r1 = r0 + 8;
    float s0 = 0.f, s1 = 0.f;
    if (r0 < N) { float id = (float)g_deg[MAX_N + r0]; s0 = rsqrtf(id) / id; }
    if (r1 < N) { float id = (float)g_deg[MAX_N + r1]; s1 = rsqrtf(id) / id; }

    #pragma unroll
    for (int nb = 0; nb < 16; nb++) {
        int col = nb * 8 + (lane & 3) * 2;
        float b0 = __ldg(bias + col);
        float b1 = __ldg(bias + col + 1);
        if (r0 < N) {
            float2 o = make_float2(acc[nb][0] * s0 + b0, acc[nb][1] * s0 + b1);
            *reinterpret_cast<float2*>(out + (size_t)r0 * D + col) = o;
        }
        if (r1 < N) {
            float2 o = make_float2(acc[nb][2] * s1 + b0, acc[nb][3] * s1 + b1);
            *reinterpret_cast<float2*>(out + (size_t)r1 * D + col) = o;
        }
    }
}

// ---------------------------------------------------------------------------
extern "C" void kernel_launch(void* const* d_in, const int* in_sizes, int n_in,
                              void* d_out, int out_size) {
    const float* h    = (const float*)d_in[0];
    const int*   src  = (const int*)  d_in[1];
    const int*   dst  = (const int*)  d_in[2];
    const int*   dist = (const int*)  d_in[3];
    const float* W    = (const float*)d_in[4];
    const float* bias = (const float*)d_in[5];
    float*       out  = (float*)d_out;

    int N = in_sizes[0] / D;
    int E = in_sizes[1];

    void* deg_p;
    cudaGetSymbolAddress(&deg_p, g_deg);
    cudaMemsetAsync(deg_p, 0, 2 * MAX_N * sizeof(int));

    int dthreads = (E + 1) / 2;
    int aggN4 = N * (D / 8);     // uint4 count of g_agg
    degree_kernel<<<(dthreads + 255) / 256, 256>>>(src, dst, E, aggN4);

    int nh = (N * (D / 8) + 255) / 256;
    prep_kernel<<<nh + 8, 256>>>(h, W, N, nh);

    int Ehalf = (E + 1) / 2;
    long long sthreads = (long long)Ehalf * 16;
    scatter_kernel<<<(unsigned)((sthreads + 255) / 256), 256>>>(src, dst, dist, E, Ehalf);

    int smem_bytes = 2 * 128 * ROWP * sizeof(__half);  // ~68 KB
    cudaFuncSetAttribute(gemm_kernel,
                         cudaFuncAttributeMaxDynamicSharedMemorySize, smem_bytes);
    gemm_kernel<<<(N + 127) / 128, 256, smem_bytes>>>(bias, out, N);
}

// round 17
// speedup vs baseline: 1.1874x; 1.0283x over previous
#include <cuda_runtime.h>
#include <cuda_fp16.h>
#include <cstdint>

#define D 128
#define MAX_N 50176
#define MAX_E 810000
#define ROWP (D + 8)           // padded half-row: 136 halves = 272B

__device__ __half g_hs[(size_t)MAX_N * D];     // half(h * outdeg^-0.5)
__device__ __half g_agg[(size_t)MAX_N * D];    // f16 atomic accumulator
__device__ __half g_wh[D * D];                 // half(W)
__device__ int    g_deg[2 * MAX_N];            // [0,MAX_N): outdeg  [MAX_N,..): indeg

// ---------------------------------------------------------------------------
// 1: degree counts (int2, 2 edges/thread) + fused g_agg zeroing
// ---------------------------------------------------------------------------
__global__ void degree_kernel(const int* __restrict__ src,
                              const int* __restrict__ dst, int E, int aggN4) {
    int i = blockIdx.x * blockDim.x + threadIdx.x;
    int total = gridDim.x * blockDim.x;

    for (int j = i; j < aggN4; j += total)
        reinterpret_cast<uint4*>(g_agg)[j] = make_uint4(0, 0, 0, 0);

    int e = i * 2;
    if (e + 1 < E) {
        int2 s2 = *reinterpret_cast<const int2*>(src + e);
        int2 d2 = *reinterpret_cast<const int2*>(dst + e);
        atomicAdd(&g_deg[s2.x], 1);
        atomicAdd(&g_deg[s2.y], 1);
        atomicAdd(&g_deg[MAX_N + d2.x], 1);
        atomicAdd(&g_deg[MAX_N + d2.y], 1);
    } else if (e < E) {
        atomicAdd(&g_deg[src[e]], 1);
        atomicAdd(&g_deg[MAX_N + dst[e]], 1);
    }
}

// ---------------------------------------------------------------------------
// 2: fused prep: blocks [0, nh) scale h -> f16;  blocks [nh, nh+8) convert W
// ---------------------------------------------------------------------------
__global__ void prep_kernel(const float* __restrict__ h,
                            const float* __restrict__ W, int N, int nh) {
    if ((int)blockIdx.x >= nh) {
        int idx = (blockIdx.x - nh) * blockDim.x + threadIdx.x;
        if (idx >= D * D / 8) return;
        const float4* wp = reinterpret_cast<const float4*>(W) + (size_t)idx * 2;
        float4 a = wp[0];
        float4 b = wp[1];
        __half2 packs[4];
        packs[0] = __floats2half2_rn(a.x, a.y);
        packs[1] = __floats2half2_rn(a.z, a.w);
        packs[2] = __floats2half2_rn(b.x, b.y);
        packs[3] = __floats2half2_rn(b.z, b.w);
        reinterpret_cast<uint4*>(g_wh)[idx] = *reinterpret_cast<uint4*>(packs);
        return;
    }
    int idx = blockIdx.x * blockDim.x + threadIdx.x;
    if (idx >= N * (D / 8)) return;
    int row = idx >> 4;
    float s = rsqrtf((float)g_deg[row]);
    const float4* hp = reinterpret_cast<const float4*>(h) + (size_t)idx * 2;
    float4 a = hp[0];
    float4 b = hp[1];
    __half2 packs[4];
    packs[0] = __floats2half2_rn(a.x * s, a.y * s);
    packs[1] = __floats2half2_rn(a.z * s, a.w * s);
    packs[2] = __floats2half2_rn(b.x * s, b.y * s);
    packs[3] = __floats2half2_rn(b.z * s, b.w * s);
    reinterpret_cast<uint4*>(g_hs)[idx] = *reinterpret_cast<uint4*>(packs);
}

// ---------------------------------------------------------------------------
// 3: edge scatter, 16 lanes/edge, 2 edges per thread  [R12 proven form]
// ---------------------------------------------------------------------------
__global__ void scatter_kernel(const int* __restrict__ src,
                               const int* __restrict__ dst,
                               const int* __restrict__ dist, int E, int Ehalf) {
    int gid  = blockIdx.x * blockDim.x + threadIdx.x;
    int e1   = gid >> 4;
    int lane = gid & 15;
    if (e1 >= Ehalf) return;
    int e2 = e1 + Ehalf;
    bool has2 = (e2 < E);

    int s1  = __ldg(src + e1);
    int d1  = __ldg(dst + e1);
    int di1 = __ldg(dist + e1);
    int s2 = 0, d2 = 0, di2 = 0;
    if (has2) {
        s2  = __ldg(src + e2);
        d2  = __ldg(dst + e2);
        di2 = __ldg(dist + e2);
    }

    uint4 v1 = reinterpret_cast<const uint4*>(g_hs + (size_t)s1 * D)[lane];
    uint4 v2 = make_uint4(0, 0, 0, 0);
    if (has2)
        v2 = reinterpret_cast<const uint4*>(g_hs + (size_t)s2 * D)[lane];

    __half2 w1 = __float2half2_rn(__int_as_float((127 - di1) << 23));
    __half2* hv1 = reinterpret_cast<__half2*>(&v1);
    hv1[0] = __hmul2(hv1[0], w1);
    hv1[1] = __hmul2(hv1[1], w1);
    hv1[2] = __hmul2(hv1[2], w1);
    hv1[3] = __hmul2(hv1[3], w1);
    __half* p1 = g_agg + (size_t)d1 * D + lane * 8;
    asm volatile("red.global.add.noftz.v4.f16x2 [%0], {%1,%2,%3,%4};"
                 :: "l"(p1), "r"(v1.x), "r"(v1.y), "r"(v1.z), "r"(v1.w)
                 : "memory");

    if (has2) {
        __half2 w2 = __float2half2_rn(__int_as_float((127 - di2) << 23));
        __half2* hv2 = reinterpret_cast<__half2*>(&v2);
        hv2[0] = __hmul2(hv2[0], w2);
        hv2[1] = __hmul2(hv2[1], w2);
        hv2[2] = __hmul2(hv2[2], w2);
        hv2[3] = __hmul2(hv2[3], w2);
        __half* p2 = g_agg + (size_t)d2 * D + lane * 8;
        asm volatile("red.global.add.noftz.v4.f16x2 [%0], {%1,%2,%3,%4};"
                     :: "l"(p2), "r"(v2.x), "r"(v2.y), "r"(v2.z), "r"(v2.w)
                     : "memory");
    }
}

// ---------------------------------------------------------------------------
// 4: tensor-core GEMM [R12 layout] with cp.async tile fills
// ---------------------------------------------------------------------------
__device__ __forceinline__ uint32_t smem_u32(const void* p) {
    return (uint32_t)__cvta_generic_to_shared(p);
}

__global__ __launch_bounds__(256)
void gemm_kernel(const float* __restrict__ bias, float* __restrict__ out, int N) {
    extern __shared__ __half sm[];
    __half* As = sm;                 // [128][ROWP]
    __half* Ws = sm + 128 * ROWP;    // [k][n] padded
    int tid  = threadIdx.x;
    int row0 = blockIdx.x * 128;

    uint32_t As_u = smem_u32(As);
    uint32_t Ws_u = smem_u32(Ws);

    // A tile via cp.async (DRAM; issue first, zero-fill OOB rows), then Ws (L2)
    #pragma unroll
    for (int jj = 0; jj < 8; jj++) {
        int i  = tid + jj * 256;
        int m  = i >> 4;
        int c8 = (i & 15) * 8;
        int grow = row0 + m;
        const __half* gsrc = g_agg + (size_t)grow * D + c8;
        uint32_t dst_a = As_u + (uint32_t)(m * ROWP + c8) * 2;
        int srcsz = (grow < N) ? 16 : 0;
        asm volatile("cp.async.cg.shared.global [%0], [%1], 16, %2;"
                     :: "r"(dst_a), "l"(gsrc), "r"(srcsz));
    }
    #pragma unroll
    for (int jj = 0; jj < 8; jj++) {
        int i  = tid + jj * 256;
        int k  = i >> 4;
        int c8 = (i & 15) * 8;
        const __half* gsrc = g_wh + i * 8;
        uint32_t dst_w = Ws_u + (uint32_t)(k * ROWP + c8) * 2;
        asm volatile("cp.async.cg.shared.global [%0], [%1], 16;"
                     :: "r"(dst_w), "l"(gsrc));
    }
    asm volatile("cp.async.commit_group;");
    asm volatile("cp.async.wait_group 0;");
    __syncthreads();

    int wid  = tid >> 5;
    int lane = tid & 31;
    int mrow = wid * 16;

    float acc[16][4];
    #pragma unroll
    for (int nb = 0; nb < 16; nb++)
        #pragma unroll
        for (int j = 0; j < 4; j++) acc[nb][j] = 0.f;

    int lr = lane & 15;
    int lc = (lane >> 4) << 3;
    int bg = lane >> 3;
    int br = lane & 7;

    #pragma unroll
    for (int kk = 0; kk < 8; kk++) {
        uint32_t a_addr = As_u + (uint32_t)(((mrow + lr) * ROWP) + kk * 16 + lc) * 2;
        uint32_t a0, a1, a2, a3;
        asm volatile("ldmatrix.sync.aligned.m8n8.x4.shared.b16 {%0,%1,%2,%3}, [%4];"
                     : "=r"(a0), "=r"(a1), "=r"(a2), "=r"(a3) : "r"(a_addr));
        #pragma unroll
        for (int nb2 = 0; nb2 < 8; nb2++) {
            int brow = kk * 16 + (bg & 1) * 8 + br;
            int bcol = nb2 * 16 + (bg >> 1) * 8;
            uint32_t b_addr = Ws_u + (uint32_t)(brow * ROWP + bcol) * 2;
            uint32_t b0, b1, b2, b3;
            asm volatile("ldmatrix.sync.aligned.m8n8.x4.trans.shared.b16 {%0,%1,%2,%3}, [%4];"
                         : "=r"(b0), "=r"(b1), "=r"(b2), "=r"(b3) : "r"(b_addr));
            asm volatile("mma.sync.aligned.m16n8k16.row.col.f32.f16.f16.f32 "
                         "{%0,%1,%2,%3},{%4,%5,%6,%7},{%8,%9},{%0,%1,%2,%3};"
                         : "+f"(acc[nb2 * 2][0]), "+f"(acc[nb2 * 2][1]),
                           "+f"(acc[nb2 * 2][2]), "+f"(acc[nb2 * 2][3])
                         : "r"(a0), "r"(a1), "r"(a2), "r"(a3), "r"(b0), "r"(b1));
            asm volatile("mma.sync.aligned.m16n8k16.row.col.f32.f16.f16.f32 "
                         "{%0,%1,%2,%3},{%4,%5,%6,%7},{%8,%9},{%0,%1,%2,%3};"
                         : "+f"(acc[nb2 * 2 + 1][0]), "+f"(acc[nb2 * 2 + 1][1]),
                           "+f"(acc[nb2 * 2 + 1][2]), "+f"(acc[nb2 * 2 + 1][3])
                         : "r"(a0), "r"(a1), "r"(a2), "r"(a3), "r"(b2), "r"(b3));
        }
    }

    int r0 = row0 + mrow + (lane >> 2);
    int r1 = r0 + 8;
    float s0 = 0.f, s1 = 0.f;
    if (r0 < N) { float id = (float)g_deg[MAX_N + r0]; s0 = rsqrtf(id) / id; }
    if (r1 < N) { float id = (float)g_deg[MAX_N + r1]; s1 = rsqrtf(id) / id; }

    #pragma unroll
    for (int nb = 0; nb < 16; nb++) {
        int col = nb * 8 + (lane & 3) * 2;
        float b0 = __ldg(bias + col);
        float b1 = __ldg(bias + col + 1);
        if (r0 < N) {
            float2 o = make_float2(acc[nb][0] * s0 + b0, acc[nb][1] * s0 + b1);
            *reinterpret_cast<float2*>(out + (size_t)r0 * D + col) = o;
        }
        if (r1 < N) {
            float2 o = make_float2(acc[nb][2] * s1 + b0, acc[nb][3] * s1 + b1);
            *reinterpret_cast<float2*>(out + (size_t)r1 * D + col) = o;
        }
    }
}

// ---------------------------------------------------------------------------
extern "C" void kernel_launch(void* const* d_in, const int* in_sizes, int n_in,
                              void* d_out, int out_size) {
    const float* h    = (const float*)d_in[0];
    const int*   src  = (const int*)  d_in[1];
    const int*   dst  = (const int*)  d_in[2];
    const int*   dist = (const int*)  d_in[3];
    const float* W    = (const float*)d_in[4];
    const float* bias = (const float*)d_in[5];
    float*       out  = (float*)d_out;

    int N = in_sizes[0] / D;
    int E = in_sizes[1];

    void* deg_p;
    cudaGetSymbolAddress(&deg_p, g_deg);
    cudaMemsetAsync(deg_p, 0, 2 * MAX_N * sizeof(int));

    int dthreads = (E + 1) / 2;
    int aggN4 = N * (D / 8);
    degree_kernel<<<(dthreads + 255) / 256, 256>>>(src, dst, E, aggN4);

    int nh = (N * (D / 8) + 255) / 256;
    prep_kernel<<<nh + 8, 256>>>(h, W, N, nh);

    int Ehalf = (E + 1) / 2;
    long long sthreads = (long long)Ehalf * 16;
    scatter_kernel<<<(unsigned)((sthreads + 255) / 256), 256>>>(src, dst, dist, E, Ehalf);

    int smem_bytes = 2 * 128 * ROWP * sizeof(__half);  // ~68 KB
    cudaFuncSetAttribute(gemm_kernel,
                         cudaFuncAttributeMaxDynamicSharedMemorySize, smem_bytes);
    gemm_kernel<<<(N + 127) / 128, 256, smem_bytes>>>(bias, out, N);
}